// round 1
// baseline (speedup 1.0000x reference)
#include <cuda_runtime.h>
#include <math.h>

#define DIM 64
#define FIN 32
#define MAXN 50048
#define MAXE 60032
#define MAXB 256
#define PW 68   // padded row stride (floats) for shared weight tiles

// ---------------- device scratch (no allocations allowed) ----------------
__device__ float g_ew[DIM * DIM];          // EW[i*64+o] (constant edge weight matrix)
__device__ float g_feat2[MAXN * DIM];      // double buffer for node features
__device__ int   g_deg[MAXN];
__device__ int   g_rowptr[MAXN + 1];
__device__ int   g_cursor[MAXN];
__device__ int   g_csrsrc[MAXE];
__device__ float g_e[MAXN];
__device__ float g_hl[MAXB * DIM];
__device__ float g_cl[MAXB * DIM];
__device__ float g_qstar[MAXB * 2 * DIM];
__device__ int   g_gstart[MAXB + 1];

__device__ __forceinline__ float sigmoidf_(float x) { return 1.0f / (1.0f + expf(-x)); }

// ---------------- EW = relu(nn1_w + nn1_b) @ nn2_w^T + nn2_b -------------
__global__ void k_compute_ew(const float* __restrict__ nn1_w, const float* __restrict__ nn1_b,
                             const float* __restrict__ nn2_w, const float* __restrict__ nn2_b) {
    __shared__ float hid[DIM];
    int t = threadIdx.x;
    if (t < DIM) hid[t] = fmaxf(nn1_w[t] + nn1_b[t], 0.0f);
    __syncthreads();
    int k = blockIdx.x * 64 + t;   // 0..4095
    float acc = nn2_b[k];
#pragma unroll
    for (int d = 0; d < DIM; d++) acc += hid[d] * nn2_w[k * DIM + d];
    g_ew[k] = acc;
}

// ---------------- degree / CSR build ----------------
__global__ void k_zero_deg(int N) {
    int i = blockIdx.x * blockDim.x + threadIdx.x;
    if (i < N) g_deg[i] = 0;
}
__global__ void k_count_deg(const int* __restrict__ dst, int E) {
    int e = blockIdx.x * blockDim.x + threadIdx.x;
    if (e < E) atomicAdd(&g_deg[dst[e]], 1);
}
__global__ void k_scan(int N) {  // single block, 1024 threads: exclusive scan of g_deg
    __shared__ int sh[1024];
    int t = threadIdx.x;
    int carry = 0;
    for (int base = 0; base < N; base += 1024) {
        int v = (base + t < N) ? g_deg[base + t] : 0;
        sh[t] = v;
        __syncthreads();
        for (int off = 1; off < 1024; off <<= 1) {
            int x = (t >= off) ? sh[t - off] : 0;
            __syncthreads();
            sh[t] += x;
            __syncthreads();
        }
        if (base + t < N) {
            int ex = carry + sh[t] - v;
            g_rowptr[base + t] = ex;
            g_cursor[base + t] = ex;
        }
        carry += sh[1023];
        __syncthreads();
    }
    if (t == 0) g_rowptr[N] = carry;
}
__global__ void k_fill_csr(const int* __restrict__ src, const int* __restrict__ dst, int E) {
    int e = blockIdx.x * blockDim.x + threadIdx.x;
    if (e < E) {
        int pos = atomicAdd(&g_cursor[dst[e]], 1);
        g_csrsrc[pos] = src[e];
    }
}

// ---------------- lin0: feat = relu(x @ W^T + b) ----------------
__global__ void k_lin0(const float* __restrict__ x, const float* __restrict__ w,
                       const float* __restrict__ b, float* __restrict__ feat, int N) {
    __shared__ float sw[DIM * 33];  // padded to kill bank conflicts
    __shared__ float sb[DIM];
    __shared__ float sx[16 * FIN];
    int t = threadIdx.x;
    for (int i = t; i < DIM * FIN; i += 256) sw[(i / FIN) * 33 + (i % FIN)] = w[i];
    if (t < DIM) sb[t] = b[t];
    __syncthreads();
    int d = t & 63, tq = t >> 6;
    for (int tile = blockIdx.x * 16; tile < N; tile += gridDim.x * 16) {
        for (int i = t; i < 16 * FIN; i += 256) {
            int n = tile + i / FIN;
            sx[i] = (n < N) ? x[n * FIN + (i % FIN)] : 0.0f;
        }
        __syncthreads();
#pragma unroll
        for (int k = 0; k < 4; k++) {
            int loc = tq * 4 + k;
            int n = tile + loc;
            if (n < N) {
                float acc = sb[d];
                const float* xr = &sx[loc * FIN];
#pragma unroll
                for (int f = 0; f < FIN; f++) acc += xr[f] * sw[d * 33 + f];
                feat[n * DIM + d] = fmaxf(acc, 0.0f);
            }
        }
        __syncthreads();
    }
}

// ---------------- fused gather + NNConv + GRU iteration ----------------
// shared layout (floats)
#define OFF_EWT 0
#define OFF_WIH (OFF_EWT + DIM * PW)
#define OFF_WHH (OFF_WIH + 3 * DIM * PW)
#define OFF_CB  (OFF_WHH + 3 * DIM * PW)
#define OFF_BIH (OFF_CB + DIM)
#define OFF_BHH (OFF_BIH + 3 * DIM)
#define OFF_S   (OFF_BHH + 3 * DIM)
#define OFF_H   (OFF_S + 16 * DIM)
#define OFF_M   (OFF_H + 16 * DIM)
#define SMEM_ITER_FLOATS (OFF_M + 16 * DIM)

__global__ void __launch_bounds__(256, 1)
k_iter(const float* __restrict__ fin, float* __restrict__ fout,
       const float* __restrict__ wih, const float* __restrict__ whh,
       const float* __restrict__ bih, const float* __restrict__ bhh,
       const float* __restrict__ convb, int N) {
    extern __shared__ float sm[];
    float* sEWt = sm + OFF_EWT;   // [64][PW], EWt[d][i] = EW[i][d]
    float* sWih = sm + OFF_WIH;   // [192][PW]
    float* sWhh = sm + OFF_WHH;   // [192][PW]
    float* sCb  = sm + OFF_CB;
    float* sBih = sm + OFF_BIH;
    float* sBhh = sm + OFF_BHH;
    float* sS   = sm + OFF_S;     // [16][64]
    float* sH   = sm + OFF_H;     // [16][64]
    float* sM   = sm + OFF_M;     // [16][64]

    int t = threadIdx.x;
    for (int i = t; i < DIM * DIM; i += 256) {
        int ii = i >> 6, d = i & 63;
        sEWt[d * PW + ii] = g_ew[ii * DIM + d];
    }
    for (int i = t; i < 3 * DIM * DIM; i += 256) {
        int g = i >> 6, o = i & 63;
        sWih[g * PW + o] = wih[i];
        sWhh[g * PW + o] = whh[i];
    }
    if (t < DIM) sCb[t] = convb[t];
    for (int i = t; i < 3 * DIM; i += 256) { sBih[i] = bih[i]; sBhh[i] = bhh[i]; }
    __syncthreads();

    int d = t & 63, tq = t >> 6;

    for (int tile = blockIdx.x * 16; tile < N; tile += gridDim.x * 16) {
        // ---- gather: sS = inv_deg * sum_{e in CSR} fin[src], sH = fin[node]
#pragma unroll
        for (int k = 0; k < 4; k++) {
            int loc = tq * 4 + k;
            int n = tile + loc;
            float s = 0.0f, h = 0.0f;
            if (n < N) {
                h = fin[n * DIM + d];
                int r0 = g_rowptr[n], r1 = g_rowptr[n + 1];
                for (int e = r0; e < r1; e++) s += fin[g_csrsrc[e] * DIM + d];
                int cnt = r1 - r0;
                s *= (cnt > 0) ? (1.0f / (float)cnt) : 0.0f;
            }
            sS[loc * DIM + d] = s;
            sH[loc * DIM + d] = h;
        }
        __syncthreads();

        // ---- stage A: m = relu(s @ EW + conv_b)
        float accA0 = 0.f, accA1 = 0.f, accA2 = 0.f, accA3 = 0.f;
        for (int i = 0; i < DIM; i += 4) {
            float4 w = *(const float4*)&sEWt[d * PW + i];
            float4 s0 = *(const float4*)&sS[(tq * 4 + 0) * DIM + i];
            float4 s1 = *(const float4*)&sS[(tq * 4 + 1) * DIM + i];
            float4 s2 = *(const float4*)&sS[(tq * 4 + 2) * DIM + i];
            float4 s3 = *(const float4*)&sS[(tq * 4 + 3) * DIM + i];
            accA0 += s0.x * w.x + s0.y * w.y + s0.z * w.z + s0.w * w.w;
            accA1 += s1.x * w.x + s1.y * w.y + s1.z * w.z + s1.w * w.w;
            accA2 += s2.x * w.x + s2.y * w.y + s2.z * w.z + s2.w * w.w;
            accA3 += s3.x * w.x + s3.y * w.y + s3.z * w.z + s3.w * w.w;
        }
        sM[(tq * 4 + 0) * DIM + d] = fmaxf(accA0 + sCb[d], 0.0f);
        sM[(tq * 4 + 1) * DIM + d] = fmaxf(accA1 + sCb[d], 0.0f);
        sM[(tq * 4 + 2) * DIM + d] = fmaxf(accA2 + sCb[d], 0.0f);
        sM[(tq * 4 + 3) * DIM + d] = fmaxf(accA3 + sCb[d], 0.0f);
        __syncthreads();

        // ---- stage B: GRU gates
        float air[4] = {0, 0, 0, 0}, aiz[4] = {0, 0, 0, 0}, ain[4] = {0, 0, 0, 0};
        float ahr[4] = {0, 0, 0, 0}, ahz[4] = {0, 0, 0, 0}, ahn[4] = {0, 0, 0, 0};
        for (int i = 0; i < DIM; i += 4) {
            float4 wr = *(const float4*)&sWih[(d)       * PW + i];
            float4 wz = *(const float4*)&sWih[(64 + d)  * PW + i];
            float4 wn = *(const float4*)&sWih[(128 + d) * PW + i];
            float4 vr = *(const float4*)&sWhh[(d)       * PW + i];
            float4 vz = *(const float4*)&sWhh[(64 + d)  * PW + i];
            float4 vn = *(const float4*)&sWhh[(128 + d) * PW + i];
#pragma unroll
            for (int k = 0; k < 4; k++) {
                float4 m4 = *(const float4*)&sM[(tq * 4 + k) * DIM + i];
                float4 h4 = *(const float4*)&sH[(tq * 4 + k) * DIM + i];
                air[k] += m4.x * wr.x + m4.y * wr.y + m4.z * wr.z + m4.w * wr.w;
                aiz[k] += m4.x * wz.x + m4.y * wz.y + m4.z * wz.z + m4.w * wz.w;
                ain[k] += m4.x * wn.x + m4.y * wn.y + m4.z * wn.z + m4.w * wn.w;
                ahr[k] += h4.x * vr.x + h4.y * vr.y + h4.z * vr.z + h4.w * vr.w;
                ahz[k] += h4.x * vz.x + h4.y * vz.y + h4.z * vz.z + h4.w * vz.w;
                ahn[k] += h4.x * vn.x + h4.y * vn.y + h4.z * vn.z + h4.w * vn.w;
            }
        }
#pragma unroll
        for (int k = 0; k < 4; k++) {
            int loc = tq * 4 + k;
            int n = tile + loc;
            if (n < N) {
                float r = sigmoidf_(air[k] + sBih[d] + ahr[k] + sBhh[d]);
                float z = sigmoidf_(aiz[k] + sBih[64 + d] + ahz[k] + sBhh[64 + d]);
                float nn = tanhf(ain[k] + sBih[128 + d] + r * (ahn[k] + sBhh[128 + d]));
                float hold = sH[loc * DIM + d];
                fout[n * DIM + d] = (1.0f - z) * nn + z * hold;
            }
        }
        __syncthreads();
    }
}

// ---------------- graph boundaries (batch is sorted) ----------------
__global__ void k_bound_init(int N, int B) {
    int i = blockIdx.x * blockDim.x + threadIdx.x;
    if (i <= B) g_gstart[i] = N;
}
__global__ void k_bound_mark(const int* __restrict__ batch, int N) {
    int i = blockIdx.x * blockDim.x + threadIdx.x;
    if (i < N) {
        if (i == 0 || batch[i - 1] != batch[i]) atomicMin(&g_gstart[batch[i]], i);
    }
}
__global__ void k_bound_fix(int B, int N) {
    g_gstart[B] = N;
    for (int b = B - 1; b >= 0; b--)
        if (g_gstart[b] > g_gstart[b + 1]) g_gstart[b] = g_gstart[b + 1];
}

// ---------------- Set2Set ----------------
__global__ void k_init_s2s(int B) {
    int i = blockIdx.x * blockDim.x + threadIdx.x;
    if (i < B * DIM) { g_hl[i] = 0.0f; g_cl[i] = 0.0f; }
    if (i < B * 2 * DIM) g_qstar[i] = 0.0f;
}

__global__ void k_lstm(const float* __restrict__ wih, const float* __restrict__ whh,
                       const float* __restrict__ bih, const float* __restrict__ bhh) {
    int b = blockIdx.x;
    int d = threadIdx.x;  // 64
    __shared__ float q[2 * DIM];
    __shared__ float h[DIM];
    h[d] = g_hl[b * DIM + d];
    q[d] = g_qstar[b * 2 * DIM + d];
    q[DIM + d] = g_qstar[b * 2 * DIM + DIM + d];
    __syncthreads();
    float gate[4];
#pragma unroll
    for (int gi = 0; gi < 4; gi++) {
        int row = gi * DIM + d;
        float acc = bih[row] + bhh[row];
        const float* wr = &wih[row * 2 * DIM];
#pragma unroll 8
        for (int j = 0; j < 2 * DIM; j++) acc += q[j] * wr[j];
        const float* vr = &whh[row * DIM];
#pragma unroll 8
        for (int j = 0; j < DIM; j++) acc += h[j] * vr[j];
        gate[gi] = acc;
    }
    float ig = sigmoidf_(gate[0]);
    float fg = sigmoidf_(gate[1]);
    float gg = tanhf(gate[2]);
    float og = sigmoidf_(gate[3]);
    float c = fg * g_cl[b * DIM + d] + ig * gg;
    g_cl[b * DIM + d] = c;
    g_hl[b * DIM + d] = og * tanhf(c);
}

__global__ void k_dote(const float* __restrict__ feat, const int* __restrict__ batch, int N) {
    int gw = (blockIdx.x * blockDim.x + threadIdx.x) >> 5;
    int lane = threadIdx.x & 31;
    if (gw >= N) return;
    int b = batch[gw];
    float v = feat[gw * DIM + lane] * g_hl[b * DIM + lane]
            + feat[gw * DIM + 32 + lane] * g_hl[b * DIM + 32 + lane];
#pragma unroll
    for (int off = 16; off > 0; off >>= 1) v += __shfl_xor_sync(0xFFFFFFFFu, v, off);
    if (lane == 0) g_e[gw] = v;
}

__global__ void k_attn(const float* __restrict__ feat) {
    int b = blockIdx.x;
    int t = threadIdx.x;  // 256
    int s0 = g_gstart[b], s1 = g_gstart[b + 1];
    __shared__ float red[256];
    __shared__ float red2[4][DIM];
    // pass 1: max
    float mx = -1e30f;
    for (int n = s0 + t; n < s1; n += 256) mx = fmaxf(mx, g_e[n]);
    red[t] = mx;
    __syncthreads();
    for (int off = 128; off > 0; off >>= 1) {
        if (t < off) red[t] = fmaxf(red[t], red[t + off]);
        __syncthreads();
    }
    float emax = (s1 > s0) ? red[0] : 0.0f;
    __syncthreads();
    // pass 2: sum of exp
    float sme = 0.0f;
    for (int n = s0 + t; n < s1; n += 256) sme += expf(g_e[n] - emax);
    red[t] = sme;
    __syncthreads();
    for (int off = 128; off > 0; off >>= 1) {
        if (t < off) red[t] += red[t + off];
        __syncthreads();
    }
    float scale = 1.0f / (red[0] + 1e-16f);
    __syncthreads();
    // pass 3: r_vec = sum a * feat
    int d = t & 63, tq = t >> 6;
    float acc = 0.0f;
    for (int n = s0 + tq; n < s1; n += 4) {
        float a = expf(g_e[n] - emax) * scale;
        acc += a * feat[n * DIM + d];
    }
    red2[tq][d] = acc;
    __syncthreads();
    if (t < DIM) {
        float r = red2[0][t] + red2[1][t] + red2[2][t] + red2[3][t];
        g_qstar[b * 2 * DIM + DIM + t] = r;
        g_qstar[b * 2 * DIM + t] = g_hl[b * DIM + t];
    }
}

__global__ void k_copy_out(float* __restrict__ out, int B) {
    int i = blockIdx.x * blockDim.x + threadIdx.x;
    if (i < B * 2 * DIM) out[i] = g_qstar[i];
}

// ---------------- launch ----------------
extern "C" void kernel_launch(void* const* d_in, const int* in_sizes, int n_in,
                              void* d_out, int out_size) {
    const float* x        = (const float*)d_in[0];
    const int*   ei       = (const int*)d_in[1];
    const int*   batch    = (const int*)d_in[2];
    const float* lin0_w   = (const float*)d_in[3];
    const float* lin0_b   = (const float*)d_in[4];
    const float* nn1_w    = (const float*)d_in[5];
    const float* nn1_b    = (const float*)d_in[6];
    const float* nn2_w    = (const float*)d_in[7];
    const float* nn2_b    = (const float*)d_in[8];
    const float* conv_b   = (const float*)d_in[9];
    const float* gru_w_ih = (const float*)d_in[10];
    const float* gru_w_hh = (const float*)d_in[11];
    const float* gru_b_ih = (const float*)d_in[12];
    const float* gru_b_hh = (const float*)d_in[13];
    const float* lstm_w_ih = (const float*)d_in[14];
    const float* lstm_w_hh = (const float*)d_in[15];
    const float* lstm_b_ih = (const float*)d_in[16];
    const float* lstm_b_hh = (const float*)d_in[17];

    int N = in_sizes[2];
    int E = in_sizes[1] / 2;
    int B = (out_size - N * DIM) / (2 * DIM);

    float* out  = (float*)d_out;
    float* feat = out + B * 2 * DIM;   // feat_map region of d_out (double buffer A)

    float* feat2 = nullptr;
    cudaGetSymbolAddress((void**)&feat2, g_feat2);  // double buffer B

    const int* src = ei;
    const int* dst = ei + E;

    const size_t smem_iter = SMEM_ITER_FLOATS * sizeof(float);
    cudaFuncSetAttribute(k_iter, cudaFuncAttributeMaxDynamicSharedMemorySize, (int)smem_iter);

    // edge weight matrix (constant across edges/iterations)
    k_compute_ew<<<64, 64>>>(nn1_w, nn1_b, nn2_w, nn2_b);

    // CSR build (edges constant across iterations)
    k_zero_deg<<<(N + 255) / 256, 256>>>(N);
    k_count_deg<<<(E + 255) / 256, 256>>>(dst, E);
    k_scan<<<1, 1024>>>(N);
    k_fill_csr<<<(E + 255) / 256, 256>>>(src, dst, E);

    // lin0 into buffer B so the 3 iterations end in d_out's feat region
    k_lin0<<<148, 256>>>(x, lin0_w, lin0_b, feat2, N);

    k_iter<<<148, 256, smem_iter>>>(feat2, feat, gru_w_ih, gru_w_hh, gru_b_ih, gru_b_hh, conv_b, N);
    k_iter<<<148, 256, smem_iter>>>(feat, feat2, gru_w_ih, gru_w_hh, gru_b_ih, gru_b_hh, conv_b, N);
    k_iter<<<148, 256, smem_iter>>>(feat2, feat, gru_w_ih, gru_w_hh, gru_b_ih, gru_b_hh, conv_b, N);

    // graph boundaries + Set2Set state init
    k_bound_init<<<(B + 256) / 256 + 1, 256>>>(N, B);
    k_bound_mark<<<(N + 255) / 256, 256>>>(batch, N);
    k_bound_fix<<<1, 1>>>(B, N);
    k_init_s2s<<<(B * 2 * DIM + 255) / 256, 256>>>(B);

    for (int step = 0; step < 3; step++) {
        k_lstm<<<B, 64>>>(lstm_w_ih, lstm_w_hh, lstm_b_ih, lstm_b_hh);
        k_dote<<<(N * 32 + 255) / 256, 256>>>(feat, batch, N);
        k_attn<<<B, 256>>>(feat);
    }
    k_copy_out<<<(B * 2 * DIM + 255) / 256, 256>>>(out, B);
}

// round 2
// speedup vs baseline: 1.7360x; 1.7360x over previous
#include <cuda_runtime.h>
#include <math.h>

#define DIM 64
#define FIN 32
#define MAXN 50048
#define MAXE 60032
#define MAXB 256
#define PW 68    // padded weight row stride (floats)
#define PS 36    // packed activation row stride (floats): [64 dims][32 locs]

typedef unsigned long long ull;

// ---------------- device scratch ----------------
__device__ float g_ew[DIM * DIM];
__device__ float g_feat2[MAXN * DIM];
__device__ int   g_deg[MAXN];
__device__ int   g_rowptr[MAXN + 1];
__device__ int   g_cursor[MAXN];
__device__ int   g_csrsrc[MAXE];
__device__ int   g_bsum[64];
__device__ float g_e[MAXN];
__device__ int   g_gstart[MAXB + 1];

__device__ __forceinline__ float sigmoidf_(float x) { return 1.0f / (1.0f + __expf(-x)); }

__device__ __forceinline__ ull ffma2(ull a, ull b, ull c) {
    ull d;
    asm("fma.rn.f32x2 %0, %1, %2, %3;" : "=l"(d) : "l"(a), "l"(b), "l"(c));
    return d;
}
__device__ __forceinline__ ull pack2(float x) {
    ull r;
    asm("mov.b64 %0, {%1, %1};" : "=l"(r) : "r"(__float_as_uint(x)));
    return r;
}
__device__ __forceinline__ float2 unpack2(ull v) {
    float2 f;
    asm("mov.b64 {%0, %1}, %2;" : "=f"(f.x), "=f"(f.y) : "l"(v));
    return f;
}

// ---------------- EW = relu(nn1_w + nn1_b) @ nn2_w^T + nn2_b -------------
__global__ void k_compute_ew(const float* __restrict__ nn1_w, const float* __restrict__ nn1_b,
                             const float* __restrict__ nn2_w, const float* __restrict__ nn2_b) {
    __shared__ float hid[DIM];
    int t = threadIdx.x;
    if (t < DIM) hid[t] = fmaxf(nn1_w[t] + nn1_b[t], 0.0f);
    __syncthreads();
    int k = blockIdx.x * 64 + t;
    float acc = nn2_b[k];
#pragma unroll
    for (int d = 0; d < DIM; d++) acc += hid[d] * nn2_w[k * DIM + d];
    g_ew[k] = acc;
}

// ---------------- prep: zero deg + init gstart ----------------
__global__ void k_prep1(int N, int B) {
    int i = blockIdx.x * blockDim.x + threadIdx.x;
    if (i < N) g_deg[i] = 0;
    if (i <= B) g_gstart[i] = N;
}
// count deg (over E) + mark graph starts (over N)
__global__ void k_prep2(const int* __restrict__ dst, const int* __restrict__ batch, int E, int N) {
    int i = blockIdx.x * blockDim.x + threadIdx.x;
    if (i < E) atomicAdd(&g_deg[dst[i]], 1);
    if (i < N) {
        if (i == 0 || batch[i - 1] != batch[i]) atomicMin(&g_gstart[batch[i]], i);
    }
}

// ---------------- parallel scan (3 phases) ----------------
__global__ void k_scan1(int N) {
    __shared__ int sh[1024];
    int t = threadIdx.x;
    int i = blockIdx.x * 1024 + t;
    int v = (i < N) ? g_deg[i] : 0;
    sh[t] = v;
    __syncthreads();
    for (int off = 1; off < 1024; off <<= 1) {
        int x = (t >= off) ? sh[t - off] : 0;
        __syncthreads();
        sh[t] += x;
        __syncthreads();
    }
    if (i < N) g_rowptr[i] = sh[t] - v;   // local exclusive
    if (t == 1023) g_bsum[blockIdx.x] = sh[t];
}
__global__ void k_scan2(int nb, int B, int N) {
    int t = threadIdx.x;
    if (t == 0) {
        int acc = 0;
        for (int j = 0; j < nb; j++) { int s = g_bsum[j]; g_bsum[j] = acc; acc += s; }
        g_bsum[nb] = acc;
    }
    if (t == 1) {  // bound fix (batch sorted; fill empty graphs)
        g_gstart[B] = N;
        for (int b = B - 1; b >= 0; b--)
            if (g_gstart[b] > g_gstart[b + 1]) g_gstart[b] = g_gstart[b + 1];
    }
}
__global__ void k_scan3(int N, int nb) {
    int i = blockIdx.x * blockDim.x + threadIdx.x;
    if (i < N) {
        int r = g_rowptr[i] + g_bsum[i >> 10];
        g_rowptr[i] = r;
        g_cursor[i] = r;
    }
    if (i == 0) g_rowptr[N] = g_bsum[nb];
}
__global__ void k_fill_csr(const int* __restrict__ src, const int* __restrict__ dst, int E) {
    int e = blockIdx.x * blockDim.x + threadIdx.x;
    if (e < E) {
        int pos = atomicAdd(&g_cursor[dst[e]], 1);
        g_csrsrc[pos] = src[e];
    }
}

// ---------------- lin0: feat = relu(x @ W^T + b) ----------------
__global__ void k_lin0(const float* __restrict__ x, const float* __restrict__ w,
                       const float* __restrict__ b, float* __restrict__ feat, int N) {
    __shared__ float sw[DIM * 33];
    __shared__ float sb[DIM];
    __shared__ float sx[16 * FIN];
    int t = threadIdx.x;
    for (int i = t; i < DIM * FIN; i += 256) sw[(i / FIN) * 33 + (i % FIN)] = w[i];
    if (t < DIM) sb[t] = b[t];
    __syncthreads();
    int d = t & 63, tq = t >> 6;
    for (int tile = blockIdx.x * 16; tile < N; tile += gridDim.x * 16) {
        for (int i = t; i < 16 * FIN; i += 256) {
            int n = tile + i / FIN;
            sx[i] = (n < N) ? x[n * FIN + (i % FIN)] : 0.0f;
        }
        __syncthreads();
#pragma unroll
        for (int k = 0; k < 4; k++) {
            int loc = tq * 4 + k;
            int n = tile + loc;
            if (n < N) {
                float acc = sb[d];
                const float* xr = &sx[loc * FIN];
#pragma unroll
                for (int f = 0; f < FIN; f++) acc += xr[f] * sw[d * 33 + f];
                feat[n * DIM + d] = fmaxf(acc, 0.0f);
            }
        }
        __syncthreads();
    }
}

// ---------------- fused gather + NNConv + GRU iteration (f32x2) ---------
#define TILE 32
#define OFF_EWT 0
#define OFF_WIH (OFF_EWT + DIM * PW)            // 4352
#define OFF_WHH (OFF_WIH + 3 * DIM * PW)        // 17408
#define OFF_CB  (OFF_WHH + 3 * DIM * PW)        // 30464
#define OFF_BIH (OFF_CB + DIM)                  // 30528
#define OFF_BHH (OFF_BIH + 3 * DIM)             // 30720
#define OFF_SP  (OFF_BHH + 3 * DIM)             // 30912
#define OFF_HP  (OFF_SP + DIM * PS)             // 33216
#define OFF_MP  (OFF_HP + DIM * PS)             // 35520
#define SMEM_ITER_FLOATS (OFF_MP + DIM * PS)    // 37824

__global__ void __launch_bounds__(512, 1)
k_iter(const float* __restrict__ fin, float* __restrict__ fout,
       const float* __restrict__ wih, const float* __restrict__ whh,
       const float* __restrict__ bih, const float* __restrict__ bhh,
       const float* __restrict__ convb, int N) {
    extern __shared__ float sm[];
    float* sEWt = sm + OFF_EWT;   // [64][PW]  EWt[d][i] = EW[i][d]
    float* sWih = sm + OFF_WIH;   // [192][PW]
    float* sWhh = sm + OFF_WHH;
    float* sCb  = sm + OFF_CB;
    float* sBih = sm + OFF_BIH;
    float* sBhh = sm + OFF_BHH;
    float* sSp  = sm + OFF_SP;    // [64 dims][32 locs] stride PS
    float* sHp  = sm + OFF_HP;
    float* sMp  = sm + OFF_MP;

    int t = threadIdx.x;
    for (int i = t; i < DIM * DIM; i += 512) {
        int ii = i >> 6, d = i & 63;
        sEWt[d * PW + ii] = g_ew[ii * DIM + d];
    }
    for (int i = t; i < 3 * DIM * DIM; i += 512) {
        int g = i >> 6, o = i & 63;
        sWih[g * PW + o] = wih[i];
        sWhh[g * PW + o] = whh[i];
    }
    if (t < DIM) sCb[t] = convb[t];
    if (t < 3 * DIM) { sBih[t] = bih[t]; sBhh[t] = bhh[t]; }
    __syncthreads();

    int d = t & 63, tq = t >> 6;   // tq in 0..7, uniform per warp
    int c0 = 4 * tq;

    for (int tile = blockIdx.x * TILE; tile < N; tile += gridDim.x * TILE) {
        // ---- gather: s = mean of neighbors, h = own features; store packed
        float sv[4], hv[4];
#pragma unroll
        for (int k = 0; k < 4; k++) {
            int n = tile + c0 + k;
            float s = 0.0f, h = 0.0f;
            if (n < N) {
                h = fin[n * DIM + d];
                int r0 = g_rowptr[n], r1 = g_rowptr[n + 1];
                for (int e = r0; e < r1; e++) s += fin[g_csrsrc[e] * DIM + d];
                int cnt = r1 - r0;
                s *= (cnt > 0) ? (1.0f / (float)cnt) : 0.0f;
            }
            sv[k] = s; hv[k] = h;
        }
        *(float4*)&sSp[d * PS + c0] = make_float4(sv[0], sv[1], sv[2], sv[3]);
        *(float4*)&sHp[d * PS + c0] = make_float4(hv[0], hv[1], hv[2], hv[3]);
        __syncthreads();

        // ---- stage A: m = relu(s @ EW + conv_b), f32x2 over node pairs
        ull a0 = 0ULL, a1 = 0ULL;
        {
            const float* wr = &sEWt[d * PW];
            const float* sp = &sSp[c0];
#pragma unroll
            for (int i = 0; i < DIM; i += 4) {
                float4 w = *(const float4*)&wr[i];
                ulonglong2 s0v = *(const ulonglong2*)&sp[(i + 0) * PS];
                ulonglong2 s1v = *(const ulonglong2*)&sp[(i + 1) * PS];
                ulonglong2 s2v = *(const ulonglong2*)&sp[(i + 2) * PS];
                ulonglong2 s3v = *(const ulonglong2*)&sp[(i + 3) * PS];
                ull w0 = pack2(w.x), w1 = pack2(w.y), w2 = pack2(w.z), w3 = pack2(w.w);
                a0 = ffma2(s0v.x, w0, a0); a1 = ffma2(s0v.y, w0, a1);
                a0 = ffma2(s1v.x, w1, a0); a1 = ffma2(s1v.y, w1, a1);
                a0 = ffma2(s2v.x, w2, a0); a1 = ffma2(s2v.y, w2, a1);
                a0 = ffma2(s3v.x, w3, a0); a1 = ffma2(s3v.y, w3, a1);
            }
        }
        {
            float cb = sCb[d];
            float2 m0 = unpack2(a0), m1 = unpack2(a1);
            *(float4*)&sMp[d * PS + c0] = make_float4(
                fmaxf(m0.x + cb, 0.0f), fmaxf(m0.y + cb, 0.0f),
                fmaxf(m1.x + cb, 0.0f), fmaxf(m1.y + cb, 0.0f));
        }
        __syncthreads();

        // ---- stage B: GRU gate matvecs, f32x2 over node pairs
        ull ir0 = 0, ir1 = 0, iz0 = 0, iz1 = 0, in0 = 0, in1 = 0;
        ull hr0 = 0, hr1 = 0, hz0 = 0, hz1 = 0, hn0 = 0, hn1 = 0;
        {
            const float* wr_ = &sWih[d * PW];
            const float* wz_ = &sWih[(64 + d) * PW];
            const float* wn_ = &sWih[(128 + d) * PW];
            const float* vr_ = &sWhh[d * PW];
            const float* vz_ = &sWhh[(64 + d) * PW];
            const float* vn_ = &sWhh[(128 + d) * PW];
            const float* mp = &sMp[c0];
            const float* hp = &sHp[c0];
#pragma unroll 4
            for (int i = 0; i < DIM; i += 4) {
                float4 wr4 = *(const float4*)&wr_[i];
                float4 wz4 = *(const float4*)&wz_[i];
                float4 wn4 = *(const float4*)&wn_[i];
                float4 vr4 = *(const float4*)&vr_[i];
                float4 vz4 = *(const float4*)&vz_[i];
                float4 vn4 = *(const float4*)&vn_[i];
                const float* pr = (const float*)&wr4;
                const float* pz = (const float*)&wz4;
                const float* pn = (const float*)&wn4;
                const float* qr = (const float*)&vr4;
                const float* qz = (const float*)&vz4;
                const float* qn = (const float*)&vn4;
#pragma unroll
                for (int ii = 0; ii < 4; ii++) {
                    ulonglong2 m2 = *(const ulonglong2*)&mp[(i + ii) * PS];
                    ulonglong2 h2 = *(const ulonglong2*)&hp[(i + ii) * PS];
                    ull wrp = pack2(pr[ii]), wzp = pack2(pz[ii]), wnp = pack2(pn[ii]);
                    ull vrp = pack2(qr[ii]), vzp = pack2(qz[ii]), vnp = pack2(qn[ii]);
                    ir0 = ffma2(m2.x, wrp, ir0); ir1 = ffma2(m2.y, wrp, ir1);
                    iz0 = ffma2(m2.x, wzp, iz0); iz1 = ffma2(m2.y, wzp, iz1);
                    in0 = ffma2(m2.x, wnp, in0); in1 = ffma2(m2.y, wnp, in1);
                    hr0 = ffma2(h2.x, vrp, hr0); hr1 = ffma2(h2.y, vrp, hr1);
                    hz0 = ffma2(h2.x, vzp, hz0); hz1 = ffma2(h2.y, vzp, hz1);
                    hn0 = ffma2(h2.x, vnp, hn0); hn1 = ffma2(h2.y, vnp, hn1);
                }
            }
        }
        // ---- epilogue
        {
            float bir = sBih[d], biz = sBih[64 + d], bin_ = sBih[128 + d];
            float bhr = sBhh[d], bhz = sBhh[64 + d], bhn = sBhh[128 + d];
            float4 hold = *(const float4*)&sHp[d * PS + c0];
            const float* hv4 = (const float*)&hold;
            float irx[4], izx[4], inx[4], hrx[4], hzx[4], hnx[4];
            { float2 u = unpack2(ir0); irx[0] = u.x; irx[1] = u.y; u = unpack2(ir1); irx[2] = u.x; irx[3] = u.y; }
            { float2 u = unpack2(iz0); izx[0] = u.x; izx[1] = u.y; u = unpack2(iz1); izx[2] = u.x; izx[3] = u.y; }
            { float2 u = unpack2(in0); inx[0] = u.x; inx[1] = u.y; u = unpack2(in1); inx[2] = u.x; inx[3] = u.y; }
            { float2 u = unpack2(hr0); hrx[0] = u.x; hrx[1] = u.y; u = unpack2(hr1); hrx[2] = u.x; hrx[3] = u.y; }
            { float2 u = unpack2(hz0); hzx[0] = u.x; hzx[1] = u.y; u = unpack2(hz1); hzx[2] = u.x; hzx[3] = u.y; }
            { float2 u = unpack2(hn0); hnx[0] = u.x; hnx[1] = u.y; u = unpack2(hn1); hnx[2] = u.x; hnx[3] = u.y; }
#pragma unroll
            for (int k = 0; k < 4; k++) {
                int n = tile + c0 + k;
                if (n < N) {
                    float r = sigmoidf_(irx[k] + bir + hrx[k] + bhr);
                    float z = sigmoidf_(izx[k] + biz + hzx[k] + bhz);
                    float nn = tanhf(inx[k] + bin_ + r * (hnx[k] + bhn));
                    fout[n * DIM + d] = (1.0f - z) * nn + z * hv4[k];
                }
            }
        }
        __syncthreads();
    }
}

// ---------------- fused Set2Set: one block per graph, 3 steps -----------
#define SWIH 132   // padded stride for lstm_w_ih rows (128 wide)
#define SWHH 68    // padded stride for lstm_w_hh rows (64 wide)
#define S2_WIH 0
#define S2_WHH (S2_WIH + 256 * SWIH)          // 33792
#define S2_BS  (S2_WHH + 256 * SWHH)          // 51200
#define S2_GATE (S2_BS + 256)                 // 51456
#define S2_RED  (S2_GATE + 256)               // 51712
#define S2_Q    (S2_RED + 256)                // 51968
#define S2_HL   (S2_Q + 128)                  // 52096
#define S2_CL   (S2_HL + 64)                  // 52160
#define S2_MISC (S2_CL + 64)                  // 52224
#define SMEM_S2S_FLOATS (S2_MISC + 4)         // 52228

__global__ void __launch_bounds__(256, 1)
k_set2set(const float* __restrict__ feat,
          const float* __restrict__ wih, const float* __restrict__ whh,
          const float* __restrict__ bih, const float* __restrict__ bhh,
          float* __restrict__ out) {
    extern __shared__ float sm[];
    float* sWih = sm + S2_WIH;   // [256][SWIH]
    float* sWhh = sm + S2_WHH;   // [256][SWHH]
    float* sBs  = sm + S2_BS;    // [256]
    float* sGate = sm + S2_GATE; // [256]
    float* sRed = sm + S2_RED;   // [256]
    float* sQ   = sm + S2_Q;     // [128]
    float* sHl  = sm + S2_HL;    // [64]
    float* sCl  = sm + S2_CL;    // [64]
    float* sMisc = sm + S2_MISC;

    int b = blockIdx.x;
    int t = threadIdx.x;
    int lane = t & 31, wid = t >> 5;

    for (int i = t; i < 256 * 128; i += 256) sWih[(i >> 7) * SWIH + (i & 127)] = wih[i];
    for (int i = t; i < 256 * 64; i += 256)  sWhh[(i >> 6) * SWHH + (i & 63)] = whh[i];
    sBs[t] = bih[t] + bhh[t];
    if (t < 128) sQ[t] = 0.0f;
    if (t < 64) { sHl[t] = 0.0f; sCl[t] = 0.0f; }
    int s0 = g_gstart[b], s1 = g_gstart[b + 1];
    __syncthreads();

    for (int step = 0; step < 3; step++) {
        // ---- LSTM cell: thread t computes gate row t
        {
            float acc = sBs[t];
            const float* wr = &sWih[t * SWIH];
#pragma unroll
            for (int j = 0; j < 128; j += 4) {
                float4 w = *(const float4*)&wr[j];
                float4 q = *(const float4*)&sQ[j];
                acc += w.x * q.x + w.y * q.y + w.z * q.z + w.w * q.w;
            }
            const float* vr = &sWhh[t * SWHH];
#pragma unroll
            for (int j = 0; j < 64; j += 4) {
                float4 w = *(const float4*)&vr[j];
                float4 h = *(const float4*)&sHl[j];
                acc += w.x * h.x + w.y * h.y + w.z * h.z + w.w * h.w;
            }
            sGate[t] = acc;
        }
        __syncthreads();
        if (t < 64) {
            float ig = sigmoidf_(sGate[t]);
            float fg = sigmoidf_(sGate[64 + t]);
            float gg = tanhf(sGate[128 + t]);
            float og = sigmoidf_(sGate[192 + t]);
            float c = fg * sCl[t] + ig * gg;
            sCl[t] = c;
            sHl[t] = og * tanhf(c);
        }
        __syncthreads();

        // ---- pass 1: e[n] = <feat[n], hl>, track max (per-warp strided)
        float mx = -1e30f;
        for (int n = s0 + wid; n < s1; n += 8) {
            float v = feat[n * DIM + lane] * sHl[lane]
                    + feat[n * DIM + 32 + lane] * sHl[32 + lane];
#pragma unroll
            for (int off = 16; off > 0; off >>= 1) v += __shfl_xor_sync(0xFFFFFFFFu, v, off);
            if (lane == 0) g_e[n] = v;
            mx = fmaxf(mx, v);
        }
        sRed[t] = mx;
        __syncthreads();
        for (int off = 128; off > 0; off >>= 1) {
            if (t < off) sRed[t] = fmaxf(sRed[t], sRed[t + off]);
            __syncthreads();
        }
        float emax = (s1 > s0) ? sRed[0] : 0.0f;
        __syncthreads();

        // ---- pass 2: sum of exp
        float sme = 0.0f;
        for (int n = s0 + t; n < s1; n += 256) sme += __expf(g_e[n] - emax);
        sRed[t] = sme;
        __syncthreads();
        for (int off = 128; off > 0; off >>= 1) {
            if (t < off) sRed[t] += sRed[t + off];
            __syncthreads();
        }
        float scale = 1.0f / (sRed[0] + 1e-16f);
        __syncthreads();

        // ---- pass 3: r = sum a * feat
        {
            int d = t & 63, tq = t >> 6;
            float acc = 0.0f;
            for (int n = s0 + tq; n < s1; n += 4) {
                float a = __expf(g_e[n] - emax) * scale;
                acc += a * feat[n * DIM + d];
            }
            sRed[t] = acc;
        }
        __syncthreads();
        if (t < 64) {
            float r = sRed[t] + sRed[64 + t] + sRed[128 + t] + sRed[192 + t];
            if (step == 2) {
                out[b * 2 * DIM + t] = sHl[t];
                out[b * 2 * DIM + DIM + t] = r;
            } else {
                sQ[t] = sHl[t];
                sQ[DIM + t] = r;
            }
        }
        __syncthreads();
    }
}

// ---------------- launch ----------------
extern "C" void kernel_launch(void* const* d_in, const int* in_sizes, int n_in,
                              void* d_out, int out_size) {
    const float* x        = (const float*)d_in[0];
    const int*   ei       = (const int*)d_in[1];
    const int*   batch    = (const int*)d_in[2];
    const float* lin0_w   = (const float*)d_in[3];
    const float* lin0_b   = (const float*)d_in[4];
    const float* nn1_w    = (const float*)d_in[5];
    const float* nn1_b    = (const float*)d_in[6];
    const float* nn2_w    = (const float*)d_in[7];
    const float* nn2_b    = (const float*)d_in[8];
    const float* conv_b   = (const float*)d_in[9];
    const float* gru_w_ih = (const float*)d_in[10];
    const float* gru_w_hh = (const float*)d_in[11];
    const float* gru_b_ih = (const float*)d_in[12];
    const float* gru_b_hh = (const float*)d_in[13];
    const float* lstm_w_ih = (const float*)d_in[14];
    const float* lstm_w_hh = (const float*)d_in[15];
    const float* lstm_b_ih = (const float*)d_in[16];
    const float* lstm_b_hh = (const float*)d_in[17];

    int N = in_sizes[2];
    int E = in_sizes[1] / 2;
    int B = (out_size - N * DIM) / (2 * DIM);

    float* out  = (float*)d_out;
    float* feat = out + B * 2 * DIM;

    float* feat2 = nullptr;
    cudaGetSymbolAddress((void**)&feat2, g_feat2);

    const int* src = ei;
    const int* dst = ei + E;

    const size_t smem_iter = SMEM_ITER_FLOATS * sizeof(float);
    const size_t smem_s2s  = SMEM_S2S_FLOATS * sizeof(float);
    cudaFuncSetAttribute(k_iter, cudaFuncAttributeMaxDynamicSharedMemorySize, (int)smem_iter);
    cudaFuncSetAttribute(k_set2set, cudaFuncAttributeMaxDynamicSharedMemorySize, (int)smem_s2s);

    int nb = (N + 1023) / 1024;
    int mx1 = (N > B + 1 ? N : B + 1);
    int mx2 = (E > N ? E : N);

    k_compute_ew<<<64, 64>>>(nn1_w, nn1_b, nn2_w, nn2_b);
    k_prep1<<<(mx1 + 255) / 256, 256>>>(N, B);
    k_prep2<<<(mx2 + 255) / 256, 256>>>(dst, batch, E, N);
    k_scan1<<<nb, 1024>>>(N);
    k_scan2<<<1, 32>>>(nb, B, N);
    k_scan3<<<(N + 255) / 256, 256>>>(N, nb);
    k_fill_csr<<<(E + 255) / 256, 256>>>(src, dst, E);

    k_lin0<<<148, 256>>>(x, lin0_w, lin0_b, feat2, N);

    k_iter<<<148, 512, smem_iter>>>(feat2, feat, gru_w_ih, gru_w_hh, gru_b_ih, gru_b_hh, conv_b, N);
    k_iter<<<148, 512, smem_iter>>>(feat, feat2, gru_w_ih, gru_w_hh, gru_b_ih, gru_b_hh, conv_b, N);
    k_iter<<<148, 512, smem_iter>>>(feat2, feat, gru_w_ih, gru_w_hh, gru_b_ih, gru_b_hh, conv_b, N);

    k_set2set<<<B, 256, smem_s2s>>>(feat, lstm_w_ih, lstm_w_hh, lstm_b_ih, lstm_b_hh, out);
}